// round 12
// baseline (speedup 1.0000x reference)
#include <cuda_runtime.h>
#include <cuda_bf16.h>

typedef unsigned int u32;
typedef unsigned long long u64;

// Fixed problem shape
#define NMAX 100000
#define QMAX 256
#define RMAX 401

// Scratch (device globals — no allocation allowed)
__device__ float g_tableSH[NMAX * 128];         // [tS row | hidden row] interleaved (51.2 MB)
__device__ float g_tableR[RMAX * 64];
__device__ float g_tableQ[QMAX * 64];
__device__ float g_tableQR[QMAX * RMAX * 64];
__device__ float g_agg[NMAX * 64];

// ---- helpers ----
__device__ __forceinline__ u32 pack_bf2(float lo, float hi) {
    __nv_bfloat162 t = __floats2bfloat162_rn(lo, hi);
    return *(u32*)&t;
}
__device__ __forceinline__ void split_bf(float x, float& hi, float& lo) {
    __nv_bfloat16 h = __float2bfloat16_rn(x);
    hi = __bfloat162float(h);
    lo = x - hi;
}
__device__ __forceinline__ u32 prmt_hi16(u32 a, u32 b) {
    u32 d;
    asm("prmt.b32 %0, %1, %2, 0x7632;" : "=r"(d) : "r"(a), "r"(b));
    return d;
}
// truncation split of 2 floats -> bf16x2 hi-pack + lo-pack
__device__ __forceinline__ void split2(float x0, float x1, u32& hp, u32& lp) {
    u32 b0 = __float_as_uint(x0), b1 = __float_as_uint(x1);
    hp = prmt_hi16(b0, b1);
    float l0 = x0 - __uint_as_float(b0 & 0xFFFF0000u);
    float l1 = x1 - __uint_as_float(b1 & 0xFFFF0000u);
    lp = prmt_hi16(__float_as_uint(l0), __float_as_uint(l1));
}

// mma.sync m16n8k16 bf16, fp32 accumulate
__device__ __forceinline__ void mma16816(float c[4], const u32 a[4], u32 b0, u32 b1) {
    asm volatile(
        "mma.sync.aligned.m16n8k16.row.col.f32.bf16.bf16.f32 "
        "{%0,%1,%2,%3}, {%4,%5,%6,%7}, {%8,%9}, {%0,%1,%2,%3};"
        : "+f"(c[0]), "+f"(c[1]), "+f"(c[2]), "+f"(c[3])
        : "r"(a[0]), "r"(a[1]), "r"(a[2]), "r"(a[3]), "r"(b0), "r"(b1));
}
__device__ __forceinline__ void ldmatrix_x4(u32 a[4], u32 addr) {
    asm volatile("ldmatrix.sync.aligned.m8n8.x4.shared.b16 {%0,%1,%2,%3}, [%4];"
                 : "=r"(a[0]), "=r"(a[1]), "=r"(a[2]), "=r"(a[3]) : "r"(addr));
}

// -----------------------------------------------------------------------------
// Persistent, double-buffered tensor-core 64x64 NT GEMM (bf16 hi/lo, 3 MMAs).
// Round-10 structure (v[8] batched staging, split accumulators, 2 CTA/SM).
// os4: out row stride in float4 (16 = dense 64, 32 = interleaved tSH).
// hcopy: if non-null (MODE 0), staging writes X rows through to hcopy[p][16..31].
// -----------------------------------------------------------------------------
template<int MODE>
__device__ __forceinline__
void gemm_body(const float* __restrict__ X,
               const float* __restrict__ qe,
               const float* __restrict__ re,
               const float* __restrict__ W,
               const float* __restrict__ bias,
               const float* __restrict__ tR,
               const float* __restrict__ tQ,
               float* __restrict__ out, int M, int R,
               float4* __restrict__ zbuf, int tiles,
               int tile0, int stride, int os4,
               float4* __restrict__ hcopy)
{
    extern __shared__ unsigned char sX[];   // [2 bufs][hi 16KB | lo 16KB] = 64 KB
    const int tid  = threadIdx.x;
    const int lane = tid & 31;
    const int w    = tid >> 5;
    const int cg   = w & 3;
    const int rg   = w >> 2;
    const int os   = os4 * 4;

    // ---- W fragments (hi/lo) in registers: built once per CTA ----
    u32 Bhi[2][4][2], Blo[2][4][2];
    {
        const int n_base = cg * 16 + (lane >> 2);
        const int k_base = (lane & 3) * 2;
        #pragma unroll
        for (int nt = 0; nt < 2; nt++) {
            #pragma unroll
            for (int ks = 0; ks < 4; ks++) {
                const float* wr = &W[(n_base + nt * 8) * 64 + ks * 16 + k_base];
                float w0 = __ldg(wr),     w1 = __ldg(wr + 1);
                float w2 = __ldg(wr + 8), w3 = __ldg(wr + 9);
                float h0, l0, h1, l1, h2, l2, h3, l3;
                split_bf(w0, h0, l0); split_bf(w1, h1, l1);
                split_bf(w2, h2, l2); split_bf(w3, h3, l3);
                Bhi[nt][ks][0] = pack_bf2(h0, h1); Bhi[nt][ks][1] = pack_bf2(h2, h3);
                Blo[nt][ks][0] = pack_bf2(l0, l1); Blo[nt][ks][1] = pack_bf2(l2, l3);
            }
        }
    }

    const u32 sb = (u32)__cvta_generic_to_shared(sX);
    const int mi = lane >> 3, lr = lane & 7;
    const int row_off = (mi & 1) * 8 + lr;
    const int kb_off  = (mi >> 1) * 16;
    const int srow = tid >> 4, sc4 = tid & 15;

    // ---- staging helpers (batched loads for MLP) ----
    auto stage_load = [&](int tile, float4 v[8]) {
        const int p0 = tile * 128 + srow;
        int q = 0, r = 0;
        if (MODE == 1) { q = p0 / R; r = p0 - q * R; }
        #pragma unroll
        for (int j = 0; j < 8; j++) {
            int p = p0 + j * 16;
            float4 t = make_float4(0.f, 0.f, 0.f, 0.f);
            if (p < M) {
                if (MODE == 0) {
                    t = __ldg(&((const float4*)X)[(size_t)p * 16 + sc4]);
                    if (zbuf) zbuf[(size_t)p * 16 + sc4] = make_float4(0.f, 0.f, 0.f, 0.f);
                    if (hcopy) hcopy[(size_t)p * 32 + 16 + sc4] = t;
                } else {
                    float4 a = __ldg(&((const float4*)qe)[q * 16 + sc4]);
                    float4 b = __ldg(&((const float4*)re)[r * 16 + sc4]);
                    t = make_float4(a.x * b.x, a.y * b.y, a.z * b.z, a.w * b.w);
                }
            }
            v[j] = t;
            if (MODE == 1) { r += 16; if (r >= R) { r -= R; q++; } }
        }
    };
    auto stage_store = [&](const float4 v[8], int buf) {
        unsigned char* base = sX + buf * 32768;
        #pragma unroll
        for (int j = 0; j < 8; j++) {
            int row = srow + j * 16;
            u32 off = (u32)(row * 128 + ((sc4 * 8) ^ ((row & 7) << 4)));
            u32 h0, l0, h1, l1;
            split2(v[j].x, v[j].y, h0, l0);
            split2(v[j].z, v[j].w, h1, l1);
            *(uint2*)(base + off)         = make_uint2(h0, h1);
            *(uint2*)(base + 16384 + off) = make_uint2(l0, l1);
        }
    };

    auto mma_epilogue = [&](int buf, int m0b) {
        const u32 hi_base = sb + buf * 32768;
        int q0 = 0, rr0 = 0, q1 = 0, rr1 = 0;
        if (MODE == 1) {
            int p0 = m0b + rg * 64 + (lane >> 2);
            q0 = p0 / R; rr0 = p0 - q0 * R;
            int p1 = p0 + 8;
            q1 = p1 / R; rr1 = p1 - q1 * R;
        }
        #pragma unroll
        for (int mt = 0; mt < 4; mt++) {
            const int mrow = rg * 64 + mt * 16;
            float accA[2][4] = {{0.f,0.f,0.f,0.f},{0.f,0.f,0.f,0.f}};
            float accB[2][4] = {{0.f,0.f,0.f,0.f},{0.f,0.f,0.f,0.f}};
            #pragma unroll
            for (int ks = 0; ks < 4; ks++) {
                const int row = mrow + row_off;
                const u32 byte = (u32)(row * 128 + ((ks * 32 + kb_off) ^ ((row & 7) << 4)));
                u32 Ahi[4], Alo[4];
                ldmatrix_x4(Ahi, hi_base + byte);
                ldmatrix_x4(Alo, hi_base + 16384 + byte);
                #pragma unroll
                for (int nt = 0; nt < 2; nt++) {
                    mma16816(accA[nt], Ahi, Bhi[nt][ks][0], Bhi[nt][ks][1]);
                    mma16816(accB[nt], Ahi, Blo[nt][ks][0], Blo[nt][ks][1]);
                    mma16816(accB[nt], Alo, Bhi[nt][ks][0], Bhi[nt][ks][1]);
                }
            }
            const int r0 = m0b + mrow + (lane >> 2);
            const int r1 = r0 + 8;
            #pragma unroll
            for (int nt = 0; nt < 2; nt++) {
                const int col = cg * 16 + nt * 8 + (lane & 3) * 2;
                float2 e0 = make_float2(accA[nt][0] + accB[nt][0], accA[nt][1] + accB[nt][1]);
                float2 e1 = make_float2(accA[nt][2] + accB[nt][2], accA[nt][3] + accB[nt][3]);
                if (MODE == 0) {
                    if (bias) {
                        float2 bv = *(const float2*)&bias[col];
                        e0.x += bv.x; e0.y += bv.y; e1.x += bv.x; e1.y += bv.y;
                    }
                } else {
                    if (r0 < M) {
                        float2 t1 = __ldg((const float2*)&tR[rr0 * 64 + col]);
                        float2 t2 = __ldg((const float2*)&tQ[q0 * 64 + col]);
                        e0.x += t1.x + t2.x; e0.y += t1.y + t2.y;
                    }
                    if (r1 < M) {
                        float2 t1 = __ldg((const float2*)&tR[rr1 * 64 + col]);
                        float2 t2 = __ldg((const float2*)&tQ[q1 * 64 + col]);
                        e1.x += t1.x + t2.x; e1.y += t1.y + t2.y;
                    }
                }
                if (r0 < M) *(float2*)&out[(size_t)r0 * os + col] = e0;
                if (r1 < M) *(float2*)&out[(size_t)r1 * os + col] = e1;
            }
            if (MODE == 1) {
                rr0 += 16; if (rr0 >= R) { rr0 -= R; q0++; }
                rr1 += 16; if (rr1 >= R) { rr1 -= R; q1++; }
            }
        }
    };

    // ---- persistent pipelined loop ----
    int tile = tile0;
    if (tile < tiles) {
        float4 v[8];
        stage_load(tile, v);
        stage_store(v, 0);
    }
    __syncthreads();
    int cur = 0;
    while (tile < tiles) {
        const int nxt = tile + stride;
        const bool have = (nxt < tiles);
        float4 v[8];
        if (have) stage_load(nxt, v);
        mma_epilogue(cur, tile * 128);
        if (have) stage_store(v, cur ^ 1);
        __syncthreads();
        cur ^= 1;
        tile = nxt;
    }
}

// ---- global wrappers ----
__global__ __launch_bounds__(256, 2)
void gemm_tc0(const float* __restrict__ X, const float* __restrict__ W,
              const float* __restrict__ bias, float* __restrict__ out,
              int M, float4* __restrict__ zbuf, int tiles, int os4,
              float4* __restrict__ hcopy)
{
    gemm_body<0>(X, nullptr, nullptr, W, bias, nullptr, nullptr,
                 out, M, 1, zbuf, tiles, blockIdx.x, gridDim.x, os4, hcopy);
}

__global__ __launch_bounds__(256, 2)
void gemm_tc1(const float* __restrict__ qe, const float* __restrict__ re,
              const float* __restrict__ W, const float* __restrict__ tR,
              const float* __restrict__ tQ, float* __restrict__ out,
              int M, int R, int tiles)
{
    gemm_body<1>(nullptr, qe, re, W, nullptr, tR, tQ,
                 out, M, R, nullptr, tiles, blockIdx.x, gridDim.x, 16, nullptr);
}

// Two independent small MODE-0 GEMMs in one launch (CTA-partitioned).
__global__ __launch_bounds__(256, 2)
void gemm_small_dual(const float* __restrict__ X1, const float* __restrict__ W1,
                     float* __restrict__ out1, int M1, int tiles1,
                     const float* __restrict__ X2, const float* __restrict__ W2,
                     float* __restrict__ out2, int M2, int tiles2)
{
    if ((int)blockIdx.x < tiles1)
        gemm_body<0>(X1, nullptr, nullptr, W1, nullptr, nullptr, nullptr,
                     out1, M1, 1, nullptr, tiles1, blockIdx.x, 1 << 20, 16, nullptr);
    else
        gemm_body<0>(X2, nullptr, nullptr, W2, nullptr, nullptr, nullptr,
                     out2, M2, 1, nullptr, tiles2, blockIdx.x - tiles1, 1 << 20, 16, nullptr);
}

// -----------------------------------------------------------------------------
// Edge kernel: persistent, 512 threads, rela cached in shared memory.
// Half-warp (16 lanes) per edge, float4 per lane. Gathers tSH (one 512B
// region per source node: [gate pre | hidden]) + tQR; hr from smem.
// -----------------------------------------------------------------------------
__global__ __launch_bounds__(512, 2)
void edge_kernel(const int* __restrict__ edges,
                 const float* __restrict__ rela,
                 const float* __restrict__ wa_W,
                 const float* __restrict__ wa_b,
                 const float* __restrict__ tSH,
                 const float* __restrict__ tQR,
                 float* __restrict__ agg,
                 float* __restrict__ alpha_out,
                 int E, int R)
{
    extern __shared__ float s_rela[];   // R*64 floats = 102656 B
    const int tid = threadIdx.x;

    for (int i = tid; i < R * 16; i += 512)
        ((float4*)s_rela)[i] = __ldg(&((const float4*)rela)[i]);
    __syncthreads();

    const int hw = tid >> 4;     // half-warp id within block: 0..31
    const int sl = tid & 15;
    const float4 wa = __ldg(&((const float4*)wa_W)[sl]);
    const float wb = __ldg(wa_b);

    for (int e0 = blockIdx.x * 64; e0 < E; e0 += gridDim.x * 64) {
        #pragma unroll
        for (int k = 0; k < 2; k++) {
            const int e = e0 + k * 32 + hw;
            if (e >= E) continue;

            const int* er = edges + (size_t)e * 6;
            const int q = __ldg(er + 0);
            const int r = __ldg(er + 2);
            const int s = __ldg(er + 4);
            const int o = __ldg(er + 5);

            float4 g  = __ldg(&((const float4*)tSH)[(size_t)s * 32 + sl]);
            float4 hs = __ldg(&((const float4*)tSH)[(size_t)s * 32 + 16 + sl]);
            float4 p2 = __ldg(&((const float4*)tQR)[((size_t)q * R + r) * 16 + sl]);
            float4 hr = *(const float4*)&s_rela[r * 64 + sl * 4];

            float px = fmaxf(g.x + p2.x, 0.f);
            float py = fmaxf(g.y + p2.y, 0.f);
            float pz = fmaxf(g.z + p2.z, 0.f);
            float pw = fmaxf(g.w + p2.w, 0.f);

            float part = fmaf(px, wa.x, fmaf(py, wa.y, fmaf(pz, wa.z, pw * wa.w)));
            #pragma unroll
            for (int off = 8; off; off >>= 1)
                part += __shfl_xor_sync(0xffffffffu, part, off);

            float alpha = 1.0f / (1.0f + __expf(-(part + wb)));
            if (sl == 0) alpha_out[e] = alpha;

            float4 m;
            m.x = alpha * hs.x * hr.x;
            m.y = alpha * hs.y * hr.y;
            m.z = alpha * hs.z * hr.z;
            m.w = alpha * hs.w * hr.w;

            float* dst = &agg[(size_t)o * 64 + sl * 4];
            asm volatile("red.global.add.v4.f32 [%0], {%1, %2, %3, %4};"
                         :: "l"(dst), "f"(m.x), "f"(m.y), "f"(m.z), "f"(m.w) : "memory");
        }
    }
}

// -----------------------------------------------------------------------------
extern "C" void kernel_launch(void* const* d_in, const int* in_sizes, int n_in,
                              void* d_out, int out_size)
{
    const float* q_emb  = (const float*)d_in[1];
    const float* rela   = (const float*)d_in[2];
    const float* hidden = (const float*)d_in[3];
    const int*   edges  = (const int*)d_in[4];
    const float* Ws_W   = (const float*)d_in[6];
    const float* Ws_b   = (const float*)d_in[7];
    const float* Wr_W   = (const float*)d_in[8];
    const float* Wq_W   = (const float*)d_in[9];
    const float* Wqr_W  = (const float*)d_in[10];
    const float* wa_W   = (const float*)d_in[11];
    const float* wa_b   = (const float*)d_in[12];
    const float* Wh_W   = (const float*)d_in[13];

    const int Q = in_sizes[0];
    const int R = in_sizes[2] / 64;
    const int N = in_sizes[3] / 64;
    const int E = in_sizes[4] / 6;

    float* out = (float*)d_out;
    float* alpha_out = out + (size_t)N * 64;

    float *tSH, *tR, *tQ, *tQR, *agg;
    cudaGetSymbolAddress((void**)&tSH, g_tableSH);
    cudaGetSymbolAddress((void**)&tR,  g_tableR);
    cudaGetSymbolAddress((void**)&tQ,  g_tableQ);
    cudaGetSymbolAddress((void**)&tQR, g_tableQR);
    cudaGetSymbolAddress((void**)&agg, g_agg);

    const int SMEM = 65536;                 // GEMM: 2 x (hi 16KB + lo 16KB)
    const int SMEM_EDGE = RMAX * 64 * 4;    // 102656 B rela cache
    cudaFuncSetAttribute(gemm_tc0, cudaFuncAttributeMaxDynamicSharedMemorySize, SMEM);
    cudaFuncSetAttribute(gemm_tc1, cudaFuncAttributeMaxDynamicSharedMemorySize, SMEM);
    cudaFuncSetAttribute(gemm_small_dual, cudaFuncAttributeMaxDynamicSharedMemorySize, SMEM);
    cudaFuncSetAttribute(edge_kernel, cudaFuncAttributeMaxDynamicSharedMemorySize, SMEM_EDGE);

    auto tiles_of = [](int M) { return (M + 127) / 128; };
    auto grid_of  = [&](int M) { int t = tiles_of(M); return t < 296 ? t : 296; };

    // Small tables (tR, tQ) in ONE launch — inputs to the QR fold
    const int tilesR = tiles_of(R), tilesQ = tiles_of(Q);
    gemm_small_dual<<<tilesR + tilesQ, 256, SMEM>>>(
        rela, Wr_W, tR, R, tilesR,
        q_emb, Wq_W, tQ, Q, tilesQ);

    // tS GEMM -> interleaved tSH (writes hidden through to the second half;
    // also zeroes agg rows)
    gemm_tc0<<<grid_of(N), 256, SMEM>>>(hidden, Ws_W, Ws_b, tSH, N,
                                        (float4*)agg, tiles_of(N), 32, (float4*)tSH);
    // tQR GEMM
    gemm_tc1<<<grid_of(Q * R), 256, SMEM>>>(q_emb, rela, Wqr_W, tR, tQ,
                                            tQR, Q * R, R, tiles_of(Q * R));

    // Per-edge gather/gate/scatter (persistent; rela in smem)
    edge_kernel<<<296, 512, SMEM_EDGE>>>(edges, rela, wa_W, wa_b,
                                         tSH, tQR, agg, alpha_out, E, R);

    // Final projection: hidden_new = agg @ Wh^T
    gemm_tc0<<<grid_of(N), 256, SMEM>>>(agg, Wh_W, nullptr, out, N,
                                        nullptr, tiles_of(N), 16, nullptr);
}

// round 13
// speedup vs baseline: 1.3189x; 1.3189x over previous
#include <cuda_runtime.h>
#include <cuda_bf16.h>

typedef unsigned int u32;
typedef unsigned long long u64;

// Fixed problem shape
#define NMAX 100000
#define QMAX 256
#define RMAX 401

// Scratch (device globals — no allocation allowed)
__device__ float g_tableS[NMAX * 64];
__device__ float g_tableR[RMAX * 64];
__device__ float g_tableQ[QMAX * 64];
__device__ float g_tableQR[QMAX * RMAX * 64];
__device__ float g_agg[NMAX * 64];

// ---- helpers ----
__device__ __forceinline__ u32 pack_bf2(float lo, float hi) {
    __nv_bfloat162 t = __floats2bfloat162_rn(lo, hi);
    return *(u32*)&t;
}
__device__ __forceinline__ void split_bf(float x, float& hi, float& lo) {
    __nv_bfloat16 h = __float2bfloat16_rn(x);
    hi = __bfloat162float(h);
    lo = x - hi;
}
__device__ __forceinline__ u32 prmt_hi16(u32 a, u32 b) {
    u32 d;
    asm("prmt.b32 %0, %1, %2, 0x7632;" : "=r"(d) : "r"(a), "r"(b));
    return d;
}
// truncation split of 2 floats -> bf16x2 hi-pack + lo-pack
__device__ __forceinline__ void split2(float x0, float x1, u32& hp, u32& lp) {
    u32 b0 = __float_as_uint(x0), b1 = __float_as_uint(x1);
    hp = prmt_hi16(b0, b1);
    float l0 = x0 - __uint_as_float(b0 & 0xFFFF0000u);
    float l1 = x1 - __uint_as_float(b1 & 0xFFFF0000u);
    lp = prmt_hi16(__float_as_uint(l0), __float_as_uint(l1));
}

// mma.sync m16n8k16 bf16, fp32 accumulate
__device__ __forceinline__ void mma16816(float c[4], const u32 a[4], u32 b0, u32 b1) {
    asm volatile(
        "mma.sync.aligned.m16n8k16.row.col.f32.bf16.bf16.f32 "
        "{%0,%1,%2,%3}, {%4,%5,%6,%7}, {%8,%9}, {%0,%1,%2,%3};"
        : "+f"(c[0]), "+f"(c[1]), "+f"(c[2]), "+f"(c[3])
        : "r"(a[0]), "r"(a[1]), "r"(a[2]), "r"(a[3]), "r"(b0), "r"(b1));
}
__device__ __forceinline__ void ldmatrix_x4(u32 a[4], u32 addr) {
    asm volatile("ldmatrix.sync.aligned.m8n8.x4.shared.b16 {%0,%1,%2,%3}, [%4];"
                 : "=r"(a[0]), "=r"(a[1]), "=r"(a[2]), "=r"(a[3]) : "r"(addr));
}

// -----------------------------------------------------------------------------
// Persistent, double-buffered tensor-core 64x64 NT GEMM (bf16 hi/lo, 3 MMAs).
// Round-10 structure: v[8] batched staging, split accumulators, 2 CTA/SM.
// MODE 0: X from gmem; optional bias; optional zbuf zeroing (fused agg clear).
// MODE 1: X row p=(q,r) = q_emb[q]*rela[r]; epilogue adds tR[r]+tQ[q].
// -----------------------------------------------------------------------------
template<int MODE>
__device__ __forceinline__
void gemm_body(const float* __restrict__ X,
               const float* __restrict__ qe,
               const float* __restrict__ re,
               const float* __restrict__ W,
               const float* __restrict__ bias,
               const float* __restrict__ tR,
               const float* __restrict__ tQ,
               float* __restrict__ out, int M, int R,
               float4* __restrict__ zbuf, int tiles,
               int tile0, int stride)
{
    extern __shared__ unsigned char sX[];   // [2 bufs][hi 16KB | lo 16KB] = 64 KB
    const int tid  = threadIdx.x;
    const int lane = tid & 31;
    const int w    = tid >> 5;
    const int cg   = w & 3;
    const int rg   = w >> 2;

    // ---- W fragments (hi/lo) in registers: built once per CTA ----
    u32 Bhi[2][4][2], Blo[2][4][2];
    {
        const int n_base = cg * 16 + (lane >> 2);
        const int k_base = (lane & 3) * 2;
        #pragma unroll
        for (int nt = 0; nt < 2; nt++) {
            #pragma unroll
            for (int ks = 0; ks < 4; ks++) {
                const float* wr = &W[(n_base + nt * 8) * 64 + ks * 16 + k_base];
                float w0 = __ldg(wr),     w1 = __ldg(wr + 1);
                float w2 = __ldg(wr + 8), w3 = __ldg(wr + 9);
                float h0, l0, h1, l1, h2, l2, h3, l3;
                split_bf(w0, h0, l0); split_bf(w1, h1, l1);
                split_bf(w2, h2, l2); split_bf(w3, h3, l3);
                Bhi[nt][ks][0] = pack_bf2(h0, h1); Bhi[nt][ks][1] = pack_bf2(h2, h3);
                Blo[nt][ks][0] = pack_bf2(l0, l1); Blo[nt][ks][1] = pack_bf2(l2, l3);
            }
        }
    }

    const u32 sb = (u32)__cvta_generic_to_shared(sX);
    const int mi = lane >> 3, lr = lane & 7;
    const int row_off = (mi & 1) * 8 + lr;
    const int kb_off  = (mi >> 1) * 16;
    const int srow = tid >> 4, sc4 = tid & 15;

    // ---- staging helpers (batched loads for MLP) ----
    auto stage_load = [&](int tile, float4 v[8]) {
        const int p0 = tile * 128 + srow;
        int q = 0, r = 0;
        if (MODE == 1) { q = p0 / R; r = p0 - q * R; }
        #pragma unroll
        for (int j = 0; j < 8; j++) {
            int p = p0 + j * 16;
            float4 t = make_float4(0.f, 0.f, 0.f, 0.f);
            if (p < M) {
                if (MODE == 0) {
                    t = __ldg(&((const float4*)X)[(size_t)p * 16 + sc4]);
                    if (zbuf) zbuf[(size_t)p * 16 + sc4] = make_float4(0.f, 0.f, 0.f, 0.f);
                } else {
                    float4 a = __ldg(&((const float4*)qe)[q * 16 + sc4]);
                    float4 b = __ldg(&((const float4*)re)[r * 16 + sc4]);
                    t = make_float4(a.x * b.x, a.y * b.y, a.z * b.z, a.w * b.w);
                }
            }
            v[j] = t;
            if (MODE == 1) { r += 16; if (r >= R) { r -= R; q++; } }
        }
    };
    auto stage_store = [&](const float4 v[8], int buf) {
        unsigned char* base = sX + buf * 32768;
        #pragma unroll
        for (int j = 0; j < 8; j++) {
            int row = srow + j * 16;
            u32 off = (u32)(row * 128 + ((sc4 * 8) ^ ((row & 7) << 4)));
            u32 h0, l0, h1, l1;
            split2(v[j].x, v[j].y, h0, l0);
            split2(v[j].z, v[j].w, h1, l1);
            *(uint2*)(base + off)         = make_uint2(h0, h1);
            *(uint2*)(base + 16384 + off) = make_uint2(l0, l1);
        }
    };

    auto mma_epilogue = [&](int buf, int m0b) {
        const u32 hi_base = sb + buf * 32768;
        int q0 = 0, rr0 = 0, q1 = 0, rr1 = 0;
        if (MODE == 1) {
            int p0 = m0b + rg * 64 + (lane >> 2);
            q0 = p0 / R; rr0 = p0 - q0 * R;
            int p1 = p0 + 8;
            q1 = p1 / R; rr1 = p1 - q1 * R;
        }
        #pragma unroll
        for (int mt = 0; mt < 4; mt++) {
            const int mrow = rg * 64 + mt * 16;
            float accA[2][4] = {{0.f,0.f,0.f,0.f},{0.f,0.f,0.f,0.f}};
            float accB[2][4] = {{0.f,0.f,0.f,0.f},{0.f,0.f,0.f,0.f}};
            #pragma unroll
            for (int ks = 0; ks < 4; ks++) {
                const int row = mrow + row_off;
                const u32 byte = (u32)(row * 128 + ((ks * 32 + kb_off) ^ ((row & 7) << 4)));
                u32 Ahi[4], Alo[4];
                ldmatrix_x4(Ahi, hi_base + byte);
                ldmatrix_x4(Alo, hi_base + 16384 + byte);
                #pragma unroll
                for (int nt = 0; nt < 2; nt++) {
                    mma16816(accA[nt], Ahi, Bhi[nt][ks][0], Bhi[nt][ks][1]);
                    mma16816(accB[nt], Ahi, Blo[nt][ks][0], Blo[nt][ks][1]);
                    mma16816(accB[nt], Alo, Bhi[nt][ks][0], Bhi[nt][ks][1]);
                }
            }
            const int r0 = m0b + mrow + (lane >> 2);
            const int r1 = r0 + 8;
            #pragma unroll
            for (int nt = 0; nt < 2; nt++) {
                const int col = cg * 16 + nt * 8 + (lane & 3) * 2;
                float2 e0 = make_float2(accA[nt][0] + accB[nt][0], accA[nt][1] + accB[nt][1]);
                float2 e1 = make_float2(accA[nt][2] + accB[nt][2], accA[nt][3] + accB[nt][3]);
                if (MODE == 0) {
                    if (bias) {
                        float2 bv = *(const float2*)&bias[col];
                        e0.x += bv.x; e0.y += bv.y; e1.x += bv.x; e1.y += bv.y;
                    }
                } else {
                    if (r0 < M) {
                        float2 t1 = __ldg((const float2*)&tR[rr0 * 64 + col]);
                        float2 t2 = __ldg((const float2*)&tQ[q0 * 64 + col]);
                        e0.x += t1.x + t2.x; e0.y += t1.y + t2.y;
                    }
                    if (r1 < M) {
                        float2 t1 = __ldg((const float2*)&tR[rr1 * 64 + col]);
                        float2 t2 = __ldg((const float2*)&tQ[q1 * 64 + col]);
                        e1.x += t1.x + t2.x; e1.y += t1.y + t2.y;
                    }
                }
                if (r0 < M) *(float2*)&out[(size_t)r0 * 64 + col] = e0;
                if (r1 < M) *(float2*)&out[(size_t)r1 * 64 + col] = e1;
            }
            if (MODE == 1) {
                rr0 += 16; if (rr0 >= R) { rr0 -= R; q0++; }
                rr1 += 16; if (rr1 >= R) { rr1 -= R; q1++; }
            }
        }
    };

    // ---- persistent pipelined loop ----
    int tile = tile0;
    if (tile < tiles) {
        float4 v[8];
        stage_load(tile, v);
        stage_store(v, 0);
    }
    __syncthreads();
    int cur = 0;
    while (tile < tiles) {
        const int nxt = tile + stride;
        const bool have = (nxt < tiles);
        float4 v[8];
        if (have) stage_load(nxt, v);
        mma_epilogue(cur, tile * 128);
        if (have) stage_store(v, cur ^ 1);
        __syncthreads();
        cur ^= 1;
        tile = nxt;
    }
}

// ---- global wrappers ----
__global__ __launch_bounds__(256, 2)
void gemm_tc0(const float* __restrict__ X, const float* __restrict__ W,
              const float* __restrict__ bias, float* __restrict__ out,
              int M, float4* __restrict__ zbuf, int tiles)
{
    gemm_body<0>(X, nullptr, nullptr, W, bias, nullptr, nullptr,
                 out, M, 1, zbuf, tiles, blockIdx.x, gridDim.x);
}

__global__ __launch_bounds__(256, 2)
void gemm_tc1(const float* __restrict__ qe, const float* __restrict__ re,
              const float* __restrict__ W, const float* __restrict__ tR,
              const float* __restrict__ tQ, float* __restrict__ out,
              int M, int R, int tiles)
{
    gemm_body<1>(nullptr, qe, re, W, nullptr, tR, tQ,
                 out, M, R, nullptr, tiles, blockIdx.x, gridDim.x);
}

// Two independent small MODE-0 GEMMs in one launch (CTA-partitioned).
__global__ __launch_bounds__(256, 2)
void gemm_small_dual(const float* __restrict__ X1, const float* __restrict__ W1,
                     float* __restrict__ out1, int M1, int tiles1,
                     const float* __restrict__ X2, const float* __restrict__ W2,
                     float* __restrict__ out2, int M2, int tiles2)
{
    if ((int)blockIdx.x < tiles1)
        gemm_body<0>(X1, nullptr, nullptr, W1, nullptr, nullptr, nullptr,
                     out1, M1, 1, nullptr, tiles1, blockIdx.x, 1 << 20);
    else
        gemm_body<0>(X2, nullptr, nullptr, W2, nullptr, nullptr, nullptr,
                     out2, M2, 1, nullptr, tiles2, blockIdx.x - tiles1, 1 << 20);
}

// -----------------------------------------------------------------------------
// Edge kernel: TWO edges per half-warp. All index loads and all 8 gathers are
// issued back-to-back (doubled MLP) before any consumption; then two gate
// reductions + two vector-atomic scatters.
// -----------------------------------------------------------------------------
__global__ __launch_bounds__(256)
void edge_kernel(const int* __restrict__ edges,
                 const float* __restrict__ hidden,
                 const float* __restrict__ rela,
                 const float* __restrict__ wa_W,
                 const float* __restrict__ wa_b,
                 const float* __restrict__ tS,
                 const float* __restrict__ tQR,
                 float* __restrict__ agg,
                 float* __restrict__ alpha_out,
                 int E, int R)
{
    const int t  = blockIdx.x * 256 + threadIdx.x;
    const int hw = t >> 4;          // global half-warp id
    const int sl = t & 15;
    const int e0 = hw * 2;
    if (e0 >= E) return;
    const int e1 = e0 + 1;
    const bool has1 = (e1 < E);

    const int* er0 = edges + (size_t)e0 * 6;
    const int* er1 = edges + (size_t)(has1 ? e1 : e0) * 6;
    const int q0 = __ldg(er0 + 0), r0 = __ldg(er0 + 2);
    const int s0 = __ldg(er0 + 4), o0 = __ldg(er0 + 5);
    const int q1 = __ldg(er1 + 0), r1 = __ldg(er1 + 2);
    const int s1 = __ldg(er1 + 4), o1 = __ldg(er1 + 5);

    // all gathers issued together (8 independent loads in flight)
    float4 g0  = __ldg(&((const float4*)tS)[(size_t)s0 * 16 + sl]);
    float4 g1  = __ldg(&((const float4*)tS)[(size_t)s1 * 16 + sl]);
    float4 p0  = __ldg(&((const float4*)tQR)[((size_t)q0 * R + r0) * 16 + sl]);
    float4 p1  = __ldg(&((const float4*)tQR)[((size_t)q1 * R + r1) * 16 + sl]);
    float4 hs0 = __ldg(&((const float4*)hidden)[(size_t)s0 * 16 + sl]);
    float4 hs1 = __ldg(&((const float4*)hidden)[(size_t)s1 * 16 + sl]);
    float4 hr0 = __ldg(&((const float4*)rela)[(size_t)r0 * 16 + sl]);
    float4 hr1 = __ldg(&((const float4*)rela)[(size_t)r1 * 16 + sl]);

    const float4 wa = __ldg(&((const float4*)wa_W)[sl]);
    const float  wb = __ldg(wa_b);

    // gate edge 0
    float a0 = fmaxf(g0.x + p0.x, 0.f), b0 = fmaxf(g0.y + p0.y, 0.f);
    float c0 = fmaxf(g0.z + p0.z, 0.f), d0 = fmaxf(g0.w + p0.w, 0.f);
    float part0 = fmaf(a0, wa.x, fmaf(b0, wa.y, fmaf(c0, wa.z, d0 * wa.w)));
    // gate edge 1
    float a1 = fmaxf(g1.x + p1.x, 0.f), b1 = fmaxf(g1.y + p1.y, 0.f);
    float c1 = fmaxf(g1.z + p1.z, 0.f), d1 = fmaxf(g1.w + p1.w, 0.f);
    float part1 = fmaf(a1, wa.x, fmaf(b1, wa.y, fmaf(c1, wa.z, d1 * wa.w)));

    #pragma unroll
    for (int off = 8; off; off >>= 1) {
        part0 += __shfl_xor_sync(0xffffffffu, part0, off);
        part1 += __shfl_xor_sync(0xffffffffu, part1, off);
    }

    const float alpha0 = 1.0f / (1.0f + __expf(-(part0 + wb)));
    const float alpha1 = 1.0f / (1.0f + __expf(-(part1 + wb)));
    if (sl == 0) {
        alpha_out[e0] = alpha0;
        if (has1) alpha_out[e1] = alpha1;
    }

    float4 m0 = make_float4(alpha0 * hs0.x * hr0.x, alpha0 * hs0.y * hr0.y,
                            alpha0 * hs0.z * hr0.z, alpha0 * hs0.w * hr0.w);
    float* dst0 = &agg[(size_t)o0 * 64 + sl * 4];
    asm volatile("red.global.add.v4.f32 [%0], {%1, %2, %3, %4};"
                 :: "l"(dst0), "f"(m0.x), "f"(m0.y), "f"(m0.z), "f"(m0.w) : "memory");

    if (has1) {
        float4 m1 = make_float4(alpha1 * hs1.x * hr1.x, alpha1 * hs1.y * hr1.y,
                                alpha1 * hs1.z * hr1.z, alpha1 * hs1.w * hr1.w);
        float* dst1 = &agg[(size_t)o1 * 64 + sl * 4];
        asm volatile("red.global.add.v4.f32 [%0], {%1, %2, %3, %4};"
                     :: "l"(dst1), "f"(m1.x), "f"(m1.y), "f"(m1.z), "f"(m1.w) : "memory");
    }
}

// -----------------------------------------------------------------------------
extern "C" void kernel_launch(void* const* d_in, const int* in_sizes, int n_in,
                              void* d_out, int out_size)
{
    const float* q_emb  = (const float*)d_in[1];
    const float* rela   = (const float*)d_in[2];
    const float* hidden = (const float*)d_in[3];
    const int*   edges  = (const int*)d_in[4];
    const float* Ws_W   = (const float*)d_in[6];
    const float* Ws_b   = (const float*)d_in[7];
    const float* Wr_W   = (const float*)d_in[8];
    const float* Wq_W   = (const float*)d_in[9];
    const float* Wqr_W  = (const float*)d_in[10];
    const float* wa_W   = (const float*)d_in[11];
    const float* wa_b   = (const float*)d_in[12];
    const float* Wh_W   = (const float*)d_in[13];

    const int Q = in_sizes[0];
    const int R = in_sizes[2] / 64;
    const int N = in_sizes[3] / 64;
    const int E = in_sizes[4] / 6;

    float* out = (float*)d_out;
    float* alpha_out = out + (size_t)N * 64;

    float *tS, *tR, *tQ, *tQR, *agg;
    cudaGetSymbolAddress((void**)&tS,  g_tableS);
    cudaGetSymbolAddress((void**)&tR,  g_tableR);
    cudaGetSymbolAddress((void**)&tQ,  g_tableQ);
    cudaGetSymbolAddress((void**)&tQR, g_tableQR);
    cudaGetSymbolAddress((void**)&agg, g_agg);

    const int SMEM = 65536;   // 2 x (hi 16KB + lo 16KB)
    cudaFuncSetAttribute(gemm_tc0, cudaFuncAttributeMaxDynamicSharedMemorySize, SMEM);
    cudaFuncSetAttribute(gemm_tc1, cudaFuncAttributeMaxDynamicSharedMemorySize, SMEM);
    cudaFuncSetAttribute(gemm_small_dual, cudaFuncAttributeMaxDynamicSharedMemorySize, SMEM);

    auto tiles_of = [](int M) { return (M + 127) / 128; };
    auto grid_of  = [&](int M) { int t = tiles_of(M); return t < 296 ? t : 296; };

    // Small tables (tR, tQ) in ONE launch — inputs to the QR fold
    const int tilesR = tiles_of(R), tilesQ = tiles_of(Q);
    gemm_small_dual<<<tilesR + tilesQ, 256, SMEM>>>(
        rela, Wr_W, tR, R, tilesR,
        q_emb, Wq_W, tQ, Q, tilesQ);

    // Big precomputes (tS pass also zeroes agg rows)
    gemm_tc0<<<grid_of(N), 256, SMEM>>>(hidden, Ws_W, Ws_b, tS, N,
                                        (float4*)agg, tiles_of(N));
    gemm_tc1<<<grid_of(Q * R), 256, SMEM>>>(q_emb, rela, Wqr_W, tR, tQ,
                                            tQR, Q * R, R, tiles_of(Q * R));

    // Per-edge gather/gate/scatter (two edges per half-warp for MLP)
    const int halfwarps = (E + 1) / 2;
    edge_kernel<<<(halfwarps + 15) / 16, 256>>>(edges, hidden, rela, wa_W, wa_b,
                                                tS, tQR, agg, alpha_out, E, R);

    // Final projection: hidden_new = agg @ Wh^T
    gemm_tc0<<<grid_of(N), 256, SMEM>>>(agg, Wh_W, nullptr, out, N,
                                        nullptr, tiles_of(N));
}

// round 14
// speedup vs baseline: 1.4289x; 1.0834x over previous
#include <cuda_runtime.h>
#include <cuda_bf16.h>

typedef unsigned int u32;
typedef unsigned long long u64;

// Fixed problem shape
#define NMAX 100000
#define QMAX 256
#define RMAX 401

// Scratch (device globals — no allocation allowed)
__device__ float g_tableS[NMAX * 64];
__device__ float g_tableR[RMAX * 64];
__device__ float g_tableQ[QMAX * 64];
__device__ float g_tableQR[QMAX * RMAX * 64];
__device__ float g_agg[NMAX * 64];

// ---- helpers ----
__device__ __forceinline__ u32 pack_bf2(float lo, float hi) {
    __nv_bfloat162 t = __floats2bfloat162_rn(lo, hi);
    return *(u32*)&t;
}
__device__ __forceinline__ void split_bf(float x, float& hi, float& lo) {
    __nv_bfloat16 h = __float2bfloat16_rn(x);
    hi = __bfloat162float(h);
    lo = x - hi;
}
__device__ __forceinline__ u32 prmt_hi16(u32 a, u32 b) {
    u32 d;
    asm("prmt.b32 %0, %1, %2, 0x7632;" : "=r"(d) : "r"(a), "r"(b));
    return d;
}
// truncation split of 2 floats -> bf16x2 hi-pack + lo-pack
__device__ __forceinline__ void split2(float x0, float x1, u32& hp, u32& lp) {
    u32 b0 = __float_as_uint(x0), b1 = __float_as_uint(x1);
    hp = prmt_hi16(b0, b1);
    float l0 = x0 - __uint_as_float(b0 & 0xFFFF0000u);
    float l1 = x1 - __uint_as_float(b1 & 0xFFFF0000u);
    lp = prmt_hi16(__float_as_uint(l0), __float_as_uint(l1));
}

// mma.sync m16n8k16 bf16, fp32 accumulate
__device__ __forceinline__ void mma16816(float c[4], const u32 a[4], u32 b0, u32 b1) {
    asm volatile(
        "mma.sync.aligned.m16n8k16.row.col.f32.bf16.bf16.f32 "
        "{%0,%1,%2,%3}, {%4,%5,%6,%7}, {%8,%9}, {%0,%1,%2,%3};"
        : "+f"(c[0]), "+f"(c[1]), "+f"(c[2]), "+f"(c[3])
        : "r"(a[0]), "r"(a[1]), "r"(a[2]), "r"(a[3]), "r"(b0), "r"(b1));
}
__device__ __forceinline__ void ldmatrix_x4(u32 a[4], u32 addr) {
    asm volatile("ldmatrix.sync.aligned.m8n8.x4.shared.b16 {%0,%1,%2,%3}, [%4];"
                 : "=r"(a[0]), "=r"(a[1]), "=r"(a[2]), "=r"(a[3]) : "r"(addr));
}

// -----------------------------------------------------------------------------
// Persistent, double-buffered tensor-core 64x64 NT GEMM (bf16 hi/lo, 3 MMAs).
// Round-10 structure: v[8] batched staging, split accumulators.
// MODE 0: X from gmem; optional bias; optional zbuf zeroing (fused agg clear).
// MODE 1: X row p=(q,r) = q_emb[q]*rela[r]; epilogue adds tR[r]+tQ[q].
// -----------------------------------------------------------------------------
template<int MODE>
__device__ __forceinline__
void gemm_body(const float* __restrict__ X,
               const float* __restrict__ qe,
               const float* __restrict__ re,
               const float* __restrict__ W,
               const float* __restrict__ bias,
               const float* __restrict__ tR,
               const float* __restrict__ tQ,
               float* __restrict__ out, int M, int R,
               float4* __restrict__ zbuf, int tiles,
               int tile0, int stride)
{
    extern __shared__ unsigned char sX[];   // [2 bufs][hi 16KB | lo 16KB] = 64 KB
    const int tid  = threadIdx.x;
    const int lane = tid & 31;
    const int w    = tid >> 5;
    const int cg   = w & 3;
    const int rg   = w >> 2;

    // ---- W fragments (hi/lo) in registers: built once per CTA ----
    u32 Bhi[2][4][2], Blo[2][4][2];
    {
        const int n_base = cg * 16 + (lane >> 2);
        const int k_base = (lane & 3) * 2;
        #pragma unroll
        for (int nt = 0; nt < 2; nt++) {
            #pragma unroll
            for (int ks = 0; ks < 4; ks++) {
                const float* wr = &W[(n_base + nt * 8) * 64 + ks * 16 + k_base];
                float w0 = __ldg(wr),     w1 = __ldg(wr + 1);
                float w2 = __ldg(wr + 8), w3 = __ldg(wr + 9);
                float h0, l0, h1, l1, h2, l2, h3, l3;
                split_bf(w0, h0, l0); split_bf(w1, h1, l1);
                split_bf(w2, h2, l2); split_bf(w3, h3, l3);
                Bhi[nt][ks][0] = pack_bf2(h0, h1); Bhi[nt][ks][1] = pack_bf2(h2, h3);
                Blo[nt][ks][0] = pack_bf2(l0, l1); Blo[nt][ks][1] = pack_bf2(l2, l3);
            }
        }
    }

    const u32 sb = (u32)__cvta_generic_to_shared(sX);
    const int mi = lane >> 3, lr = lane & 7;
    const int row_off = (mi & 1) * 8 + lr;
    const int kb_off  = (mi >> 1) * 16;
    const int srow = tid >> 4, sc4 = tid & 15;

    // ---- staging helpers (batched loads for MLP) ----
    auto stage_load = [&](int tile, float4 v[8]) {
        const int p0 = tile * 128 + srow;
        int q = 0, r = 0;
        if (MODE == 1) { q = p0 / R; r = p0 - q * R; }
        #pragma unroll
        for (int j = 0; j < 8; j++) {
            int p = p0 + j * 16;
            float4 t = make_float4(0.f, 0.f, 0.f, 0.f);
            if (p < M) {
                if (MODE == 0) {
                    t = __ldg(&((const float4*)X)[(size_t)p * 16 + sc4]);
                    if (zbuf) zbuf[(size_t)p * 16 + sc4] = make_float4(0.f, 0.f, 0.f, 0.f);
                } else {
                    float4 a = __ldg(&((const float4*)qe)[q * 16 + sc4]);
                    float4 b = __ldg(&((const float4*)re)[r * 16 + sc4]);
                    t = make_float4(a.x * b.x, a.y * b.y, a.z * b.z, a.w * b.w);
                }
            }
            v[j] = t;
            if (MODE == 1) { r += 16; if (r >= R) { r -= R; q++; } }
        }
    };
    auto stage_store = [&](const float4 v[8], int buf) {
        unsigned char* base = sX + buf * 32768;
        #pragma unroll
        for (int j = 0; j < 8; j++) {
            int row = srow + j * 16;
            u32 off = (u32)(row * 128 + ((sc4 * 8) ^ ((row & 7) << 4)));
            u32 h0, l0, h1, l1;
            split2(v[j].x, v[j].y, h0, l0);
            split2(v[j].z, v[j].w, h1, l1);
            *(uint2*)(base + off)         = make_uint2(h0, h1);
            *(uint2*)(base + 16384 + off) = make_uint2(l0, l1);
        }
    };

    auto mma_epilogue = [&](int buf, int m0b) {
        const u32 hi_base = sb + buf * 32768;
        int q0 = 0, rr0 = 0, q1 = 0, rr1 = 0;
        if (MODE == 1) {
            int p0 = m0b + rg * 64 + (lane >> 2);
            q0 = p0 / R; rr0 = p0 - q0 * R;
            int p1 = p0 + 8;
            q1 = p1 / R; rr1 = p1 - q1 * R;
        }
        #pragma unroll
        for (int mt = 0; mt < 4; mt++) {
            const int mrow = rg * 64 + mt * 16;
            float accA[2][4] = {{0.f,0.f,0.f,0.f},{0.f,0.f,0.f,0.f}};
            float accB[2][4] = {{0.f,0.f,0.f,0.f},{0.f,0.f,0.f,0.f}};
            #pragma unroll
            for (int ks = 0; ks < 4; ks++) {
                const int row = mrow + row_off;
                const u32 byte = (u32)(row * 128 + ((ks * 32 + kb_off) ^ ((row & 7) << 4)));
                u32 Ahi[4], Alo[4];
                ldmatrix_x4(Ahi, hi_base + byte);
                ldmatrix_x4(Alo, hi_base + 16384 + byte);
                #pragma unroll
                for (int nt = 0; nt < 2; nt++) {
                    mma16816(accA[nt], Ahi, Bhi[nt][ks][0], Bhi[nt][ks][1]);
                    mma16816(accB[nt], Ahi, Blo[nt][ks][0], Blo[nt][ks][1]);
                    mma16816(accB[nt], Alo, Bhi[nt][ks][0], Bhi[nt][ks][1]);
                }
            }
            const int r0 = m0b + mrow + (lane >> 2);
            const int r1 = r0 + 8;
            #pragma unroll
            for (int nt = 0; nt < 2; nt++) {
                const int col = cg * 16 + nt * 8 + (lane & 3) * 2;
                float2 e0 = make_float2(accA[nt][0] + accB[nt][0], accA[nt][1] + accB[nt][1]);
                float2 e1 = make_float2(accA[nt][2] + accB[nt][2], accA[nt][3] + accB[nt][3]);
                if (MODE == 0) {
                    if (bias) {
                        float2 bv = *(const float2*)&bias[col];
                        e0.x += bv.x; e0.y += bv.y; e1.x += bv.x; e1.y += bv.y;
                    }
                } else {
                    if (r0 < M) {
                        float2 t1 = __ldg((const float2*)&tR[rr0 * 64 + col]);
                        float2 t2 = __ldg((const float2*)&tQ[q0 * 64 + col]);
                        e0.x += t1.x + t2.x; e0.y += t1.y + t2.y;
                    }
                    if (r1 < M) {
                        float2 t1 = __ldg((const float2*)&tR[rr1 * 64 + col]);
                        float2 t2 = __ldg((const float2*)&tQ[q1 * 64 + col]);
                        e1.x += t1.x + t2.x; e1.y += t1.y + t2.y;
                    }
                }
                if (r0 < M) *(float2*)&out[(size_t)r0 * 64 + col] = e0;
                if (r1 < M) *(float2*)&out[(size_t)r1 * 64 + col] = e1;
            }
            if (MODE == 1) {
                rr0 += 16; if (rr0 >= R) { rr0 -= R; q0++; }
                rr1 += 16; if (rr1 >= R) { rr1 -= R; q1++; }
            }
        }
    };

    // ---- persistent pipelined loop ----
    int tile = tile0;
    if (tile < tiles) {
        float4 v[8];
        stage_load(tile, v);
        stage_store(v, 0);
    }
    __syncthreads();
    int cur = 0;
    while (tile < tiles) {
        const int nxt = tile + stride;
        const bool have = (nxt < tiles);
        float4 v[8];
        if (have) stage_load(nxt, v);
        mma_epilogue(cur, tile * 128);
        if (have) stage_store(v, cur ^ 1);
        __syncthreads();
        cur ^= 1;
        tile = nxt;
    }
}

// ---- global wrappers ----
__global__ __launch_bounds__(256, 2)
void gemm_tc0(const float* __restrict__ X, const float* __restrict__ W,
              const float* __restrict__ bias, float* __restrict__ out,
              int M, float4* __restrict__ zbuf, int tiles)
{
    gemm_body<0>(X, nullptr, nullptr, W, bias, nullptr, nullptr,
                 out, M, 1, zbuf, tiles, blockIdx.x, gridDim.x);
}

// Merged mid launch: first gridA CTAs run the tS GEMM (MODE 0, also zeroes
// agg); the rest run the tQR GEMM (MODE 1). Both groups co-resident ->
// double the independent latency chains per SM during the mid phase.
__global__ __launch_bounds__(256, 2)
void gemm_mid_dual(const float* __restrict__ hidden, const float* __restrict__ Ws_W,
                   const float* __restrict__ Ws_b, float* __restrict__ tS,
                   int N, float4* __restrict__ zbuf, int tilesA, int gridA,
                   const float* __restrict__ qe, const float* __restrict__ re,
                   const float* __restrict__ Wqr, const float* __restrict__ tR,
                   const float* __restrict__ tQ, float* __restrict__ tQR,
                   int MQR, int R, int tilesB)
{
    if ((int)blockIdx.x < gridA)
        gemm_body<0>(hidden, nullptr, nullptr, Ws_W, Ws_b, nullptr, nullptr,
                     tS, N, 1, zbuf, tilesA, blockIdx.x, gridA);
    else
        gemm_body<1>(nullptr, qe, re, Wqr, nullptr, tR, tQ,
                     tQR, MQR, R, nullptr, tilesB,
                     blockIdx.x - gridA, gridDim.x - gridA);
}

// Two independent small MODE-0 GEMMs in one launch (CTA-partitioned).
__global__ __launch_bounds__(256, 2)
void gemm_small_dual(const float* __restrict__ X1, const float* __restrict__ W1,
                     float* __restrict__ out1, int M1, int tiles1,
                     const float* __restrict__ X2, const float* __restrict__ W2,
                     float* __restrict__ out2, int M2, int tiles2)
{
    if ((int)blockIdx.x < tiles1)
        gemm_body<0>(X1, nullptr, nullptr, W1, nullptr, nullptr, nullptr,
                     out1, M1, 1, nullptr, tiles1, blockIdx.x, 1 << 20);
    else
        gemm_body<0>(X2, nullptr, nullptr, W2, nullptr, nullptr, nullptr,
                     out2, M2, 1, nullptr, tiles2, blockIdx.x - tiles1, 1 << 20);
}

// -----------------------------------------------------------------------------
// Edge kernel (round-10 form — local optimum): one edge per half-warp,
// float4 per lane, vector-atomic scatter.
// -----------------------------------------------------------------------------
__global__ __launch_bounds__(256)
void edge_kernel(const int* __restrict__ edges,
                 const float* __restrict__ hidden,
                 const float* __restrict__ rela,
                 const float* __restrict__ wa_W,
                 const float* __restrict__ wa_b,
                 const float* __restrict__ tS,
                 const float* __restrict__ tQR,
                 float* __restrict__ agg,
                 float* __restrict__ alpha_out,
                 int E, int R)
{
    const int t = blockIdx.x * 256 + threadIdx.x;
    const int e = t >> 4;
    if (e >= E) return;
    const int sl = t & 15;

    const int* er = edges + (size_t)e * 6;
    const int q = __ldg(er + 0);
    const int r = __ldg(er + 2);
    const int s = __ldg(er + 4);
    const int o = __ldg(er + 5);

    float4 g   = __ldg(&((const float4*)tS)[(size_t)s * 16 + sl]);
    float4 p2  = __ldg(&((const float4*)tQR)[((size_t)q * R + r) * 16 + sl]);
    float4 hs  = __ldg(&((const float4*)hidden)[(size_t)s * 16 + sl]);
    float4 hr  = __ldg(&((const float4*)rela)[(size_t)r * 16 + sl]);
    float4 wa  = __ldg(&((const float4*)wa_W)[sl]);

    float px = fmaxf(g.x + p2.x, 0.f);
    float py = fmaxf(g.y + p2.y, 0.f);
    float pz = fmaxf(g.z + p2.z, 0.f);
    float pw = fmaxf(g.w + p2.w, 0.f);

    float part = fmaf(px, wa.x, fmaf(py, wa.y, fmaf(pz, wa.z, pw * wa.w)));
    #pragma unroll
    for (int off = 8; off; off >>= 1)
        part += __shfl_xor_sync(0xffffffffu, part, off);

    float alpha = 1.0f / (1.0f + __expf(-(part + __ldg(wa_b))));
    if (sl == 0) alpha_out[e] = alpha;

    float4 m;
    m.x = alpha * hs.x * hr.x;
    m.y = alpha * hs.y * hr.y;
    m.z = alpha * hs.z * hr.z;
    m.w = alpha * hs.w * hr.w;

    float* dst = &agg[(size_t)o * 64 + sl * 4];
    asm volatile("red.global.add.v4.f32 [%0], {%1, %2, %3, %4};"
                 :: "l"(dst), "f"(m.x), "f"(m.y), "f"(m.z), "f"(m.w) : "memory");
}

// -----------------------------------------------------------------------------
extern "C" void kernel_launch(void* const* d_in, const int* in_sizes, int n_in,
                              void* d_out, int out_size)
{
    const float* q_emb  = (const float*)d_in[1];
    const float* rela   = (const float*)d_in[2];
    const float* hidden = (const float*)d_in[3];
    const int*   edges  = (const int*)d_in[4];
    const float* Ws_W   = (const float*)d_in[6];
    const float* Ws_b   = (const float*)d_in[7];
    const float* Wr_W   = (const float*)d_in[8];
    const float* Wq_W   = (const float*)d_in[9];
    const float* Wqr_W  = (const float*)d_in[10];
    const float* wa_W   = (const float*)d_in[11];
    const float* wa_b   = (const float*)d_in[12];
    const float* Wh_W   = (const float*)d_in[13];

    const int Q = in_sizes[0];
    const int R = in_sizes[2] / 64;
    const int N = in_sizes[3] / 64;
    const int E = in_sizes[4] / 6;

    float* out = (float*)d_out;
    float* alpha_out = out + (size_t)N * 64;

    float *tS, *tR, *tQ, *tQR, *agg;
    cudaGetSymbolAddress((void**)&tS,  g_tableS);
    cudaGetSymbolAddress((void**)&tR,  g_tableR);
    cudaGetSymbolAddress((void**)&tQ,  g_tableQ);
    cudaGetSymbolAddress((void**)&tQR, g_tableQR);
    cudaGetSymbolAddress((void**)&agg, g_agg);

    const int SMEM = 65536;   // 2 x (hi 16KB + lo 16KB)
    cudaFuncSetAttribute(gemm_tc0, cudaFuncAttributeMaxDynamicSharedMemorySize, SMEM);
    cudaFuncSetAttribute(gemm_mid_dual, cudaFuncAttributeMaxDynamicSharedMemorySize, SMEM);
    cudaFuncSetAttribute(gemm_small_dual, cudaFuncAttributeMaxDynamicSharedMemorySize, SMEM);

    auto tiles_of = [](int M) { return (M + 127) / 128; };
    auto grid_of  = [&](int M) { int t = tiles_of(M); return t < 296 ? t : 296; };

    // Small tables (tR, tQ) in ONE launch — inputs to the QR fold
    const int tilesR = tiles_of(R), tilesQ = tiles_of(Q);
    gemm_small_dual<<<tilesR + tilesQ, 256, SMEM>>>(
        rela, Wr_W, tR, R, tilesR,
        q_emb, Wq_W, tQ, Q, tilesQ);

    // Mid GEMMs merged: tS (also zeroes agg) and tQR run CONCURRENTLY.
    // 444 CTAs = 148 SMs x 3 (64 KB smem each -> 3 co-resident, 24 warps/SM).
    const int gridA = 222, gridB = 222;
    gemm_mid_dual<<<gridA + gridB, 256, SMEM>>>(
        hidden, Ws_W, Ws_b, tS, N, (float4*)agg, tiles_of(N), gridA,
        q_emb, rela, Wqr_W, tR, tQ, tQR, Q * R, R, tiles_of(Q * R));

    // Per-edge gather/gate/scatter (one edge per half-warp)
    edge_kernel<<<(E * 16 + 255) / 256, 256>>>(edges, hidden, rela, wa_W, wa_b,
                                               tS, tQR, agg, alpha_out, E, R);

    // Final projection: hidden_new = agg @ Wh^T
    gemm_tc0<<<grid_of(N), 256, SMEM>>>(agg, Wh_W, nullptr, out, N,
                                        nullptr, tiles_of(N));
}

// round 15
// speedup vs baseline: 1.4298x; 1.0006x over previous
#include <cuda_runtime.h>
#include <cuda_bf16.h>

typedef unsigned int u32;
typedef unsigned long long u64;

// Fixed problem shape
#define NMAX 100000
#define QMAX 256
#define RMAX 401

// Scratch (device globals — no allocation allowed)
__device__ float g_tableS[NMAX * 64];
__device__ float g_tableR[RMAX * 64];
__device__ float g_tableQ[QMAX * 64];
__device__ float g_tableQR[QMAX * RMAX * 64];
__device__ float g_agg[NMAX * 64];
__device__ int   g_flag;          // small-table completion counter (reset by final GEMM)

// ---- helpers ----
__device__ __forceinline__ u32 pack_bf2(float lo, float hi) {
    __nv_bfloat162 t = __floats2bfloat162_rn(lo, hi);
    return *(u32*)&t;
}
__device__ __forceinline__ void split_bf(float x, float& hi, float& lo) {
    __nv_bfloat16 h = __float2bfloat16_rn(x);
    hi = __bfloat162float(h);
    lo = x - hi;
}
__device__ __forceinline__ u32 prmt_hi16(u32 a, u32 b) {
    u32 d;
    asm("prmt.b32 %0, %1, %2, 0x7632;" : "=r"(d) : "r"(a), "r"(b));
    return d;
}
// truncation split of 2 floats -> bf16x2 hi-pack + lo-pack
__device__ __forceinline__ void split2(float x0, float x1, u32& hp, u32& lp) {
    u32 b0 = __float_as_uint(x0), b1 = __float_as_uint(x1);
    hp = prmt_hi16(b0, b1);
    float l0 = x0 - __uint_as_float(b0 & 0xFFFF0000u);
    float l1 = x1 - __uint_as_float(b1 & 0xFFFF0000u);
    lp = prmt_hi16(__float_as_uint(l0), __float_as_uint(l1));
}

// mma.sync m16n8k16 bf16, fp32 accumulate
__device__ __forceinline__ void mma16816(float c[4], const u32 a[4], u32 b0, u32 b1) {
    asm volatile(
        "mma.sync.aligned.m16n8k16.row.col.f32.bf16.bf16.f32 "
        "{%0,%1,%2,%3}, {%4,%5,%6,%7}, {%8,%9}, {%0,%1,%2,%3};"
        : "+f"(c[0]), "+f"(c[1]), "+f"(c[2]), "+f"(c[3])
        : "r"(a[0]), "r"(a[1]), "r"(a[2]), "r"(a[3]), "r"(b0), "r"(b1));
}
__device__ __forceinline__ void ldmatrix_x4(u32 a[4], u32 addr) {
    asm volatile("ldmatrix.sync.aligned.m8n8.x4.shared.b16 {%0,%1,%2,%3}, [%4];"
                 : "=r"(a[0]), "=r"(a[1]), "=r"(a[2]), "=r"(a[3]) : "r"(addr));
}

// -----------------------------------------------------------------------------
// Persistent, double-buffered tensor-core 64x64 NT GEMM (bf16 hi/lo, 3 MMAs).
// Round-10 structure: v[8] batched staging, split accumulators.
// MODE 0: X from gmem; optional bias; optional zbuf zeroing (fused agg clear).
// MODE 1: X row p=(q,r) = q_emb[q]*rela[r]; epilogue adds tR[r]+tQ[q].
// -----------------------------------------------------------------------------
template<int MODE>
__device__ __forceinline__
void gemm_body(const float* __restrict__ X,
               const float* __restrict__ qe,
               const float* __restrict__ re,
               const float* __restrict__ W,
               const float* __restrict__ bias,
               const float* __restrict__ tR,
               const float* __restrict__ tQ,
               float* __restrict__ out, int M, int R,
               float4* __restrict__ zbuf, int tiles,
               int tile0, int stride)
{
    extern __shared__ unsigned char sX[];   // [2 bufs][hi 16KB | lo 16KB] = 64 KB
    const int tid  = threadIdx.x;
    const int lane = tid & 31;
    const int w    = tid >> 5;
    const int cg   = w & 3;
    const int rg   = w >> 2;

    // ---- W fragments (hi/lo) in registers: built once per CTA ----
    u32 Bhi[2][4][2], Blo[2][4][2];
    {
        const int n_base = cg * 16 + (lane >> 2);
        const int k_base = (lane & 3) * 2;
        #pragma unroll
        for (int nt = 0; nt < 2; nt++) {
            #pragma unroll
            for (int ks = 0; ks < 4; ks++) {
                const float* wr = &W[(n_base + nt * 8) * 64 + ks * 16 + k_base];
                float w0 = __ldg(wr),     w1 = __ldg(wr + 1);
                float w2 = __ldg(wr + 8), w3 = __ldg(wr + 9);
                float h0, l0, h1, l1, h2, l2, h3, l3;
                split_bf(w0, h0, l0); split_bf(w1, h1, l1);
                split_bf(w2, h2, l2); split_bf(w3, h3, l3);
                Bhi[nt][ks][0] = pack_bf2(h0, h1); Bhi[nt][ks][1] = pack_bf2(h2, h3);
                Blo[nt][ks][0] = pack_bf2(l0, l1); Blo[nt][ks][1] = pack_bf2(l2, l3);
            }
        }
    }

    const u32 sb = (u32)__cvta_generic_to_shared(sX);
    const int mi = lane >> 3, lr = lane & 7;
    const int row_off = (mi & 1) * 8 + lr;
    const int kb_off  = (mi >> 1) * 16;
    const int srow = tid >> 4, sc4 = tid & 15;

    // ---- staging helpers (batched loads for MLP) ----
    auto stage_load = [&](int tile, float4 v[8]) {
        const int p0 = tile * 128 + srow;
        int q = 0, r = 0;
        if (MODE == 1) { q = p0 / R; r = p0 - q * R; }
        #pragma unroll
        for (int j = 0; j < 8; j++) {
            int p = p0 + j * 16;
            float4 t = make_float4(0.f, 0.f, 0.f, 0.f);
            if (p < M) {
                if (MODE == 0) {
                    t = __ldg(&((const float4*)X)[(size_t)p * 16 + sc4]);
                    if (zbuf) zbuf[(size_t)p * 16 + sc4] = make_float4(0.f, 0.f, 0.f, 0.f);
                } else {
                    float4 a = __ldg(&((const float4*)qe)[q * 16 + sc4]);
                    float4 b = __ldg(&((const float4*)re)[r * 16 + sc4]);
                    t = make_float4(a.x * b.x, a.y * b.y, a.z * b.z, a.w * b.w);
                }
            }
            v[j] = t;
            if (MODE == 1) { r += 16; if (r >= R) { r -= R; q++; } }
        }
    };
    auto stage_store = [&](const float4 v[8], int buf) {
        unsigned char* base = sX + buf * 32768;
        #pragma unroll
        for (int j = 0; j < 8; j++) {
            int row = srow + j * 16;
            u32 off = (u32)(row * 128 + ((sc4 * 8) ^ ((row & 7) << 4)));
            u32 h0, l0, h1, l1;
            split2(v[j].x, v[j].y, h0, l0);
            split2(v[j].z, v[j].w, h1, l1);
            *(uint2*)(base + off)         = make_uint2(h0, h1);
            *(uint2*)(base + 16384 + off) = make_uint2(l0, l1);
        }
    };

    auto mma_epilogue = [&](int buf, int m0b) {
        const u32 hi_base = sb + buf * 32768;
        int q0 = 0, rr0 = 0, q1 = 0, rr1 = 0;
        if (MODE == 1) {
            int p0 = m0b + rg * 64 + (lane >> 2);
            q0 = p0 / R; rr0 = p0 - q0 * R;
            int p1 = p0 + 8;
            q1 = p1 / R; rr1 = p1 - q1 * R;
        }
        #pragma unroll
        for (int mt = 0; mt < 4; mt++) {
            const int mrow = rg * 64 + mt * 16;
            float accA[2][4] = {{0.f,0.f,0.f,0.f},{0.f,0.f,0.f,0.f}};
            float accB[2][4] = {{0.f,0.f,0.f,0.f},{0.f,0.f,0.f,0.f}};
            #pragma unroll
            for (int ks = 0; ks < 4; ks++) {
                const int row = mrow + row_off;
                const u32 byte = (u32)(row * 128 + ((ks * 32 + kb_off) ^ ((row & 7) << 4)));
                u32 Ahi[4], Alo[4];
                ldmatrix_x4(Ahi, hi_base + byte);
                ldmatrix_x4(Alo, hi_base + 16384 + byte);
                #pragma unroll
                for (int nt = 0; nt < 2; nt++) {
                    mma16816(accA[nt], Ahi, Bhi[nt][ks][0], Bhi[nt][ks][1]);
                    mma16816(accB[nt], Ahi, Blo[nt][ks][0], Blo[nt][ks][1]);
                    mma16816(accB[nt], Alo, Bhi[nt][ks][0], Bhi[nt][ks][1]);
                }
            }
            const int r0 = m0b + mrow + (lane >> 2);
            const int r1 = r0 + 8;
            #pragma unroll
            for (int nt = 0; nt < 2; nt++) {
                const int col = cg * 16 + nt * 8 + (lane & 3) * 2;
                float2 e0 = make_float2(accA[nt][0] + accB[nt][0], accA[nt][1] + accB[nt][1]);
                float2 e1 = make_float2(accA[nt][2] + accB[nt][2], accA[nt][3] + accB[nt][3]);
                if (MODE == 0) {
                    if (bias) {
                        float2 bv = *(const float2*)&bias[col];
                        e0.x += bv.x; e0.y += bv.y; e1.x += bv.x; e1.y += bv.y;
                    }
                } else {
                    if (r0 < M) {
                        float2 t1 = __ldg((const float2*)&tR[rr0 * 64 + col]);
                        float2 t2 = __ldg((const float2*)&tQ[q0 * 64 + col]);
                        e0.x += t1.x + t2.x; e0.y += t1.y + t2.y;
                    }
                    if (r1 < M) {
                        float2 t1 = __ldg((const float2*)&tR[rr1 * 64 + col]);
                        float2 t2 = __ldg((const float2*)&tQ[q1 * 64 + col]);
                        e1.x += t1.x + t2.x; e1.y += t1.y + t2.y;
                    }
                }
                if (r0 < M) *(float2*)&out[(size_t)r0 * 64 + col] = e0;
                if (r1 < M) *(float2*)&out[(size_t)r1 * 64 + col] = e1;
            }
            if (MODE == 1) {
                rr0 += 16; if (rr0 >= R) { rr0 -= R; q0++; }
                rr1 += 16; if (rr1 >= R) { rr1 -= R; q1++; }
            }
        }
    };

    // ---- persistent pipelined loop ----
    int tile = tile0;
    if (tile < tiles) {
        float4 v[8];
        stage_load(tile, v);
        stage_store(v, 0);
    }
    __syncthreads();
    int cur = 0;
    while (tile < tiles) {
        const int nxt = tile + stride;
        const bool have = (nxt < tiles);
        float4 v[8];
        if (have) stage_load(nxt, v);
        mma_epilogue(cur, tile * 128);
        if (have) stage_store(v, cur ^ 1);
        __syncthreads();
        cur ^= 1;
        tile = nxt;
    }
}

// ---- global wrappers ----
// Final projection; also resets g_flag for the next replay (stream-ordered
// after the mid kernel's handshake, before the next call's launch).
__global__ __launch_bounds__(256, 2)
void gemm_tc0(const float* __restrict__ X, const float* __restrict__ W,
              const float* __restrict__ bias, float* __restrict__ out,
              int M, float4* __restrict__ zbuf, int tiles, int reset_flag)
{
    if (reset_flag && blockIdx.x == 0 && threadIdx.x == 0) g_flag = 0;
    gemm_body<0>(X, nullptr, nullptr, W, bias, nullptr, nullptr,
                 out, M, 1, zbuf, tiles, blockIdx.x, gridDim.x);
}

// Merged mid launch — three CTA groups:
//   [0, nSmall):           small table GEMMs (tR, tQ); release g_flag on finish
//   [nSmall, nSmall+gA):   tS GEMM (MODE 0, also zeroes agg)
//   [nSmall+gA, grid):     tQR GEMM (MODE 1); acquires g_flag before running
// Wave-1 residency of bids 0..5 is guaranteed (296 resident CTAs), no deadlock.
__global__ __launch_bounds__(256, 2)
void gemm_mid_tri(const float* __restrict__ rela_in, const float* __restrict__ Wr_W,
                  float* __restrict__ tR, int Rrows, int tilesR,
                  const float* __restrict__ qe_in, const float* __restrict__ Wq_W,
                  float* __restrict__ tQ, int Qrows, int tilesQ,
                  const float* __restrict__ hidden, const float* __restrict__ Ws_W,
                  const float* __restrict__ Ws_b, float* __restrict__ tS,
                  int N, float4* __restrict__ zbuf, int tilesA, int gridA,
                  const float* __restrict__ qe, const float* __restrict__ re,
                  const float* __restrict__ Wqr, float* __restrict__ tQR,
                  int MQR, int R, int tilesB)
{
    const int nSmall = tilesR + tilesQ;
    const int bid = blockIdx.x;

    if (bid < nSmall) {
        if (bid < tilesR)
            gemm_body<0>(rela_in, nullptr, nullptr, Wr_W, nullptr, nullptr, nullptr,
                         tR, Rrows, 1, nullptr, tilesR, bid, 1 << 20);
        else
            gemm_body<0>(qe_in, nullptr, nullptr, Wq_W, nullptr, nullptr, nullptr,
                         tQ, Qrows, 1, nullptr, tilesQ, bid - tilesR, 1 << 20);
        __threadfence();            // release: table writes visible before count
        __syncthreads();
        if (threadIdx.x == 0) atomicAdd(&g_flag, 1);
    } else if (bid < nSmall + gridA) {
        gemm_body<0>(hidden, nullptr, nullptr, Ws_W, Ws_b, nullptr, nullptr,
                     tS, N, 1, zbuf, tilesA, bid - nSmall, gridA);
    } else {
        // acquire: wait for all small-table CTAs before reading tR/tQ
        if (threadIdx.x == 0) {
            while (atomicAdd(&g_flag, 0) < nSmall) __nanosleep(200);
        }
        __syncthreads();
        __threadfence();
        gemm_body<1>(nullptr, qe, re, Wqr, nullptr, tR, tQ,
                     tQR, MQR, R, nullptr, tilesB,
                     bid - nSmall - gridA, gridDim.x - nSmall - gridA);
    }
}

// -----------------------------------------------------------------------------
// Edge kernel (round-10 form — at its floor): one edge per half-warp,
// float4 per lane, vector-atomic scatter.
// -----------------------------------------------------------------------------
__global__ __launch_bounds__(256)
void edge_kernel(const int* __restrict__ edges,
                 const float* __restrict__ hidden,
                 const float* __restrict__ rela,
                 const float* __restrict__ wa_W,
                 const float* __restrict__ wa_b,
                 const float* __restrict__ tS,
                 const float* __restrict__ tQR,
                 float* __restrict__ agg,
                 float* __restrict__ alpha_out,
                 int E, int R)
{
    const int t = blockIdx.x * 256 + threadIdx.x;
    const int e = t >> 4;
    if (e >= E) return;
    const int sl = t & 15;

    const int* er = edges + (size_t)e * 6;
    const int q = __ldg(er + 0);
    const int r = __ldg(er + 2);
    const int s = __ldg(er + 4);
    const int o = __ldg(er + 5);

    float4 g   = __ldg(&((const float4*)tS)[(size_t)s * 16 + sl]);
    float4 p2  = __ldg(&((const float4*)tQR)[((size_t)q * R + r) * 16 + sl]);
    float4 hs  = __ldg(&((const float4*)hidden)[(size_t)s * 16 + sl]);
    float4 hr  = __ldg(&((const float4*)rela)[(size_t)r * 16 + sl]);
    float4 wa  = __ldg(&((const float4*)wa_W)[sl]);

    float px = fmaxf(g.x + p2.x, 0.f);
    float py = fmaxf(g.y + p2.y, 0.f);
    float pz = fmaxf(g.z + p2.z, 0.f);
    float pw = fmaxf(g.w + p2.w, 0.f);

    float part = fmaf(px, wa.x, fmaf(py, wa.y, fmaf(pz, wa.z, pw * wa.w)));
    #pragma unroll
    for (int off = 8; off; off >>= 1)
        part += __shfl_xor_sync(0xffffffffu, part, off);

    float alpha = 1.0f / (1.0f + __expf(-(part + __ldg(wa_b))));
    if (sl == 0) alpha_out[e] = alpha;

    float4 m;
    m.x = alpha * hs.x * hr.x;
    m.y = alpha * hs.y * hr.y;
    m.z = alpha * hs.z * hr.z;
    m.w = alpha * hs.w * hr.w;

    float* dst = &agg[(size_t)o * 64 + sl * 4];
    asm volatile("red.global.add.v4.f32 [%0], {%1, %2, %3, %4};"
                 :: "l"(dst), "f"(m.x), "f"(m.y), "f"(m.z), "f"(m.w) : "memory");
}

// -----------------------------------------------------------------------------
extern "C" void kernel_launch(void* const* d_in, const int* in_sizes, int n_in,
                              void* d_out, int out_size)
{
    const float* q_emb  = (const float*)d_in[1];
    const float* rela   = (const float*)d_in[2];
    const float* hidden = (const float*)d_in[3];
    const int*   edges  = (const int*)d_in[4];
    const float* Ws_W   = (const float*)d_in[6];
    const float* Ws_b   = (const float*)d_in[7];
    const float* Wr_W   = (const float*)d_in[8];
    const float* Wq_W   = (const float*)d_in[9];
    const float* Wqr_W  = (const float*)d_in[10];
    const float* wa_W   = (const float*)d_in[11];
    const float* wa_b   = (const float*)d_in[12];
    const float* Wh_W   = (const float*)d_in[13];

    const int Q = in_sizes[0];
    const int R = in_sizes[2] / 64;
    const int N = in_sizes[3] / 64;
    const int E = in_sizes[4] / 6;

    float* out = (float*)d_out;
    float* alpha_out = out + (size_t)N * 64;

    float *tS, *tR, *tQ, *tQR, *agg;
    cudaGetSymbolAddress((void**)&tS,  g_tableS);
    cudaGetSymbolAddress((void**)&tR,  g_tableR);
    cudaGetSymbolAddress((void**)&tQ,  g_tableQ);
    cudaGetSymbolAddress((void**)&tQR, g_tableQR);
    cudaGetSymbolAddress((void**)&agg, g_agg);

    const int SMEM = 65536;   // 2 x (hi 16KB + lo 16KB)
    cudaFuncSetAttribute(gemm_tc0, cudaFuncAttributeMaxDynamicSharedMemorySize, SMEM);
    cudaFuncSetAttribute(gemm_mid_tri, cudaFuncAttributeMaxDynamicSharedMemorySize, SMEM);

    auto tiles_of = [](int M) { return (M + 127) / 128; };
    auto grid_of  = [&](int M) { int t = tiles_of(M); return t < 296 ? t : 296; };

    // Mid phase: ONE launch — small tables + tS (also zeroes agg) + tQR,
    // with in-kernel release/acquire between small tables and tQR.
    const int tilesR = tiles_of(R), tilesQ = tiles_of(Q);
    const int nSmall = tilesR + tilesQ;           // 6
    const int gridA = 200, gridB = 238;           // tS : tQR CTA split
    gemm_mid_tri<<<nSmall + gridA + gridB, 256, SMEM>>>(
        rela, Wr_W, tR, R, tilesR,
        q_emb, Wq_W, tQ, Q, tilesQ,
        hidden, Ws_W, Ws_b, tS, N, (float4*)agg, tiles_of(N), gridA,
        q_emb, rela, Wqr_W, tQR, Q * R, R, tiles_of(Q * R));

    // Per-edge gather/gate/scatter (one edge per half-warp)
    edge_kernel<<<(E * 16 + 255) / 256, 256>>>(edges, hidden, rela, wa_W, wa_b,
                                               tS, tQR, agg, alpha_out, E, R);

    // Final projection: hidden_new = agg @ Wh^T (also resets g_flag)
    gemm_tc0<<<grid_of(N), 256, SMEM>>>(agg, Wh_W, nullptr, out, N,
                                        nullptr, tiles_of(N), 1);
}